// round 5
// baseline (speedup 1.0000x reference)
#include <cuda_runtime.h>

#define N_NODES 100000
#define E_EDGES 1600000
#define D 64
#define SCAN_BS 1024
#define SCAN_NB ((N_NODES + SCAN_BS - 1) / SCAN_BS)   // 98

// ---------------- scratch (static device globals; no allocation) ------------
__device__ float g_hs [N_NODES * D];     // (h @ W) * dinv[row]
__device__ float g_h  [N_NODES * D];     // layer output ping buffer
__device__ float g_dinv[N_NODES];
__device__ int   g_cnt[N_NODES];         // in-degree counts
__device__ int   g_row_start[N_NODES + 1];
__device__ int   g_cursor[N_NODES];
__device__ int   g_srcv[E_EDGES];        // decoded src ids
__device__ int   g_dstv[E_EDGES];        // decoded dst ids
__device__ int   g_edge_src[E_EDGES];    // src ids grouped by dst (CSR)
__device__ int   g_bsum[SCAN_NB];
__device__ int   g_boff[SCAN_NB];
__device__ int   g_is64;                 // 1 if edge_index buffer is int64

// ---------------- dtype detection + edge decode -----------------------------
// int64 little-endian nonneg ids => every odd int32 word is a zero high word.
// int32 random ids => odd words are random in [0,100000): all-zero is ~1e-40.
__global__ void detect_k(const int* __restrict__ ei32) {
    if (threadIdx.x == 0 && blockIdx.x == 0) {
        int nz = 0;
        #pragma unroll
        for (int k = 0; k < 8; k++) nz |= ei32[2 * k + 1];
        g_is64 = (nz == 0) ? 1 : 0;
    }
}

__global__ void conv_k(const void* __restrict__ eiv) {
    int e = blockIdx.x * blockDim.x + threadIdx.x;
    if (e >= E_EDGES) return;
    int s, d;
    if (g_is64) {
        const long long* ei = (const long long*)eiv;
        s = (int)ei[e];
        d = (int)ei[E_EDGES + e];
    } else {
        const int* ei = (const int*)eiv;
        s = ei[e];
        d = ei[E_EDGES + e];
    }
    // clamp: any surprise becomes wrong-answer (diagnosable), never a trap
    s = min(max(s, 0), N_NODES - 1);
    d = min(max(d, 0), N_NODES - 1);
    g_srcv[e] = s;
    g_dstv[e] = d;
}

// ---------------- CSR construction ------------------------------------------
__global__ void zero_cnt_k() {
    int i = blockIdx.x * blockDim.x + threadIdx.x;
    if (i < N_NODES) g_cnt[i] = 0;
}

__global__ void hist_k() {
    int e = blockIdx.x * blockDim.x + threadIdx.x;
    if (e >= E_EDGES) return;
    atomicAdd(&g_cnt[g_dstv[e]], 1);
}

// block-local scan -> exclusive-in-block to row_start, block totals to g_bsum
__global__ void scan1_k() {
    __shared__ int s[SCAN_BS];
    int tid = threadIdx.x;
    int i = blockIdx.x * SCAN_BS + tid;
    int v = (i < N_NODES) ? g_cnt[i] : 0;
    s[tid] = v;
    __syncthreads();
    #pragma unroll
    for (int off = 1; off < SCAN_BS; off <<= 1) {
        int t = (tid >= off) ? s[tid - off] : 0;
        __syncthreads();
        s[tid] += t;
        __syncthreads();
    }
    if (i < N_NODES) g_row_start[i] = s[tid] - v;   // exclusive within block
    if (tid == SCAN_BS - 1) g_bsum[blockIdx.x] = s[tid];
}

// warp-scan of the 98 block sums (single warp, sequential chunks of 32)
__global__ void scan2_k() {
    int lane = threadIdx.x;   // 0..31
    int carry = 0;
    for (int base = 0; base < SCAN_NB; base += 32) {
        int idx = base + lane;
        int v = (idx < SCAN_NB) ? g_bsum[idx] : 0;
        int incl = v;
        #pragma unroll
        for (int off = 1; off < 32; off <<= 1) {
            int t = __shfl_up_sync(0xffffffffu, incl, off);
            if (lane >= off) incl += t;
        }
        if (idx < SCAN_NB) g_boff[idx] = carry + incl - v;  // exclusive
        carry += __shfl_sync(0xffffffffu, incl, 31);
    }
}

__global__ void scan3_k() {
    int i = blockIdx.x * blockDim.x + threadIdx.x;
    if (i < N_NODES) {
        int rs = g_row_start[i] + g_boff[i / SCAN_BS];
        g_row_start[i] = rs;
        g_cursor[i]    = rs;
        g_dinv[i]      = rsqrtf((float)g_cnt[i] + 1.0f);
    }
    if (i == 0) g_row_start[N_NODES] = E_EDGES;
}

__global__ void place_k() {
    int e = blockIdx.x * blockDim.x + threadIdx.x;
    if (e >= E_EDGES) return;
    int pos = atomicAdd(&g_cursor[g_dstv[e]], 1);
    g_edge_src[pos] = g_srcv[e];
}

// ---------------- fused GEMM: hs = (in @ W) * dinv[row] ---------------------
// 64-row x 64-col tile per block, 256 threads, 4x4 register tile per thread.
#define WPAD 68
__global__ void __launch_bounds__(256)
gemm_scale_k(const float* __restrict__ xg, const float* __restrict__ W) {
    __shared__ float Ws[64 * WPAD];
    __shared__ float xT[64 * WPAD];

    const float* in = xg ? xg : g_h;     // null sentinel -> ping buffer
    const int tid  = threadIdx.x;
    const int row0 = blockIdx.x * 64;

    for (int i4 = tid; i4 < 1024; i4 += 256) {
        float4 v = ((const float4*)W)[i4];
        int lin = i4 * 4;
        int k = lin >> 6, c = lin & 63;
        *(float4*)&Ws[k * WPAD + c] = v;
    }
    {
        int r  = tid >> 2;
        int kq = (tid & 3) * 16;
        int rg = row0 + r;
        const float4* xrow = (const float4*)(in + (size_t)rg * D);
        #pragma unroll
        for (int kk = 0; kk < 16; kk += 4) {
            float4 v = (rg < N_NODES) ? xrow[(kq + kk) >> 2]
                                      : make_float4(0.f, 0.f, 0.f, 0.f);
            int k = kq + kk;
            xT[(k + 0) * WPAD + r] = v.x;
            xT[(k + 1) * WPAD + r] = v.y;
            xT[(k + 2) * WPAD + r] = v.z;
            xT[(k + 3) * WPAD + r] = v.w;
        }
    }
    __syncthreads();

    const int c0 = (tid & 15) * 4;
    const int r0 = (tid >> 4) * 4;

    float acc[4][4];
    #pragma unroll
    for (int i = 0; i < 4; i++)
        #pragma unroll
        for (int j = 0; j < 4; j++) acc[i][j] = 0.0f;

    #pragma unroll 16
    for (int k = 0; k < 64; k++) {
        float4 wv = *(float4*)&Ws[k * WPAD + c0];
        float4 xv = *(float4*)&xT[k * WPAD + r0];
        acc[0][0] += xv.x * wv.x; acc[0][1] += xv.x * wv.y;
        acc[0][2] += xv.x * wv.z; acc[0][3] += xv.x * wv.w;
        acc[1][0] += xv.y * wv.x; acc[1][1] += xv.y * wv.y;
        acc[1][2] += xv.y * wv.z; acc[1][3] += xv.y * wv.w;
        acc[2][0] += xv.z * wv.x; acc[2][1] += xv.z * wv.y;
        acc[2][2] += xv.z * wv.z; acc[2][3] += xv.z * wv.w;
        acc[3][0] += xv.w * wv.x; acc[3][1] += xv.w * wv.y;
        acc[3][2] += xv.w * wv.z; acc[3][3] += xv.w * wv.w;
    }

    #pragma unroll
    for (int i = 0; i < 4; i++) {
        int row = row0 + r0 + i;
        if (row < N_NODES) {
            float dv = g_dinv[row];
            *(float4*)&g_hs[(size_t)row * D + c0] =
                make_float4(acc[i][0] * dv, acc[i][1] * dv,
                            acc[i][2] * dv, acc[i][3] * dv);
        }
    }
}

// ---------------- CSR gather + epilogue -------------------------------------
// One warp per node. Lane l owns float2 at columns [2l, 2l+1].
// out[i] = dinv[i] * (sum_{e in CSR[i]} hs[src_e] + hs[i]) + b   (+relu)
__global__ void __launch_bounds__(256)
agg_k(const float* __restrict__ b, float* __restrict__ outp, int relu) {
    int gw   = (blockIdx.x * blockDim.x + threadIdx.x) >> 5;
    int lane = threadIdx.x & 31;
    if (gw >= N_NODES) return;

    float* out = outp ? outp : g_h;
    const float2* hs2 = (const float2*)g_hs;

    int beg = g_row_start[gw];
    int end = g_row_start[gw + 1];

    float2 acc = __ldg(&hs2[(size_t)gw * 32 + lane]);   // self-loop term
    int e = beg;
    // 4-edge unroll: batch independent index loads, then independent data loads
    for (; e + 3 < end; e += 4) {
        int s0 = __ldg(&g_edge_src[e + 0]);
        int s1 = __ldg(&g_edge_src[e + 1]);
        int s2 = __ldg(&g_edge_src[e + 2]);
        int s3 = __ldg(&g_edge_src[e + 3]);
        float2 a0 = __ldg(&hs2[(size_t)s0 * 32 + lane]);
        float2 a1 = __ldg(&hs2[(size_t)s1 * 32 + lane]);
        float2 a2 = __ldg(&hs2[(size_t)s2 * 32 + lane]);
        float2 a3 = __ldg(&hs2[(size_t)s3 * 32 + lane]);
        acc.x += (a0.x + a1.x) + (a2.x + a3.x);
        acc.y += (a0.y + a1.y) + (a2.y + a3.y);
    }
    for (; e < end; e++) {
        int s0 = __ldg(&g_edge_src[e]);
        float2 a = __ldg(&hs2[(size_t)s0 * 32 + lane]);
        acc.x += a.x;
        acc.y += a.y;
    }

    float dv = g_dinv[gw];
    float bx = __ldg(&b[lane * 2]), by = __ldg(&b[lane * 2 + 1]);
    float ox = acc.x * dv + bx;
    float oy = acc.y * dv + by;
    if (relu) { ox = fmaxf(ox, 0.f); oy = fmaxf(oy, 0.f); }
    ((float2*)out)[(size_t)gw * 32 + lane] = make_float2(ox, oy);
}

// ---------------- launch ----------------------------------------------------
extern "C" void kernel_launch(void* const* d_in, const int* in_sizes, int n_in,
                              void* d_out, int out_size) {
    const float* x  = (const float*)d_in[0];
    const void*  ei = d_in[1];                 // int32 or int64, detected on device
    const float* W0 = (const float*)d_in[2];
    const float* b0 = (const float*)d_in[3];
    const float* W1 = (const float*)d_in[4];
    const float* b1 = (const float*)d_in[5];
    const float* W2 = (const float*)d_in[6];
    const float* b2 = (const float*)d_in[7];
    float* out = (float*)d_out;

    const int TB = 256;
    const int ngrid = (N_NODES + TB - 1) / TB;
    const int egrid = (E_EDGES + TB - 1) / TB;

    // edge decode (dtype-agnostic) + CSR build
    detect_k  <<<1, 32>>>((const int*)ei);
    conv_k    <<<egrid, TB>>>(ei);
    zero_cnt_k<<<ngrid, TB>>>();
    hist_k    <<<egrid, TB>>>();
    scan1_k   <<<SCAN_NB, SCAN_BS>>>();
    scan2_k   <<<1, 32>>>();
    scan3_k   <<<ngrid, TB>>>();
    place_k   <<<egrid, TB>>>();

    const int gemm_grid = (N_NODES + 63) / 64;
    const int agg_grid  = (N_NODES * 32 + TB - 1) / TB;   // 1 warp / node

    // layer 0
    gemm_scale_k<<<gemm_grid, TB>>>(x, W0);
    agg_k       <<<agg_grid, TB>>>(b0, nullptr, 1);
    // layer 1
    gemm_scale_k<<<gemm_grid, TB>>>(nullptr, W1);
    agg_k       <<<agg_grid, TB>>>(b1, nullptr, 1);
    // layer 2 -> d_out, no relu
    gemm_scale_k<<<gemm_grid, TB>>>(nullptr, W2);
    agg_k       <<<agg_grid, TB>>>(b2, out, 0);
}

// round 6
// speedup vs baseline: 1.0565x; 1.0565x over previous
#include <cuda_runtime.h>

#define N_NODES 100000
#define E_EDGES 1600000
#define D 64
#define SCAN_BS 1024
#define SCAN_NB ((N_NODES + SCAN_BS - 1) / SCAN_BS)   // 98

// ---------------- scratch (static device globals; no allocation) ------------
__device__ float g_hs [N_NODES * D];     // (h @ W) * dinv[row]
__device__ float g_h  [N_NODES * D];     // layer output ping buffer
__device__ float g_dinv[N_NODES];
__device__ int   g_cnt[N_NODES];         // in-degree counts
__device__ int   g_row_start[N_NODES + 1];
__device__ int   g_cursor[N_NODES];
__device__ int   g_srcv[E_EDGES];        // decoded src ids
__device__ int   g_dstv[E_EDGES];        // decoded dst ids
__device__ int   g_edge_src[E_EDGES];    // src ids grouped by dst (CSR)
__device__ int   g_bsum[SCAN_NB];
__device__ int   g_boff[SCAN_NB];
__device__ int   g_is64;                 // 1 if edge_index buffer is int64

// ---------------- dtype detection -------------------------------------------
// int64 little-endian nonneg ids => every odd int32 word is a zero high word.
__global__ void detect_k(const int* __restrict__ ei32) {
    if (threadIdx.x == 0 && blockIdx.x == 0) {
        int nz = 0;
        #pragma unroll
        for (int k = 0; k < 8; k++) nz |= ei32[2 * k + 1];
        g_is64 = (nz == 0) ? 1 : 0;
    }
}

__global__ void zero_cnt_k() {
    int i = blockIdx.x * blockDim.x + threadIdx.x;
    if (i < N_NODES) g_cnt[i] = 0;
}

// fused decode + store + degree histogram (one pass over edge buffer)
__global__ void conv_hist_k(const void* __restrict__ eiv) {
    int e = blockIdx.x * blockDim.x + threadIdx.x;
    if (e >= E_EDGES) return;
    int s, d;
    if (g_is64) {
        const long long* ei = (const long long*)eiv;
        s = (int)ei[e];
        d = (int)ei[E_EDGES + e];
    } else {
        const int* ei = (const int*)eiv;
        s = ei[e];
        d = ei[E_EDGES + e];
    }
    s = min(max(s, 0), N_NODES - 1);
    d = min(max(d, 0), N_NODES - 1);
    g_srcv[e] = s;
    g_dstv[e] = d;
    atomicAdd(&g_cnt[d], 1);
}

// block-local scan -> exclusive-in-block to row_start, block totals to g_bsum
__global__ void scan1_k() {
    __shared__ int s[SCAN_BS];
    int tid = threadIdx.x;
    int i = blockIdx.x * SCAN_BS + tid;
    int v = (i < N_NODES) ? g_cnt[i] : 0;
    s[tid] = v;
    __syncthreads();
    #pragma unroll
    for (int off = 1; off < SCAN_BS; off <<= 1) {
        int t = (tid >= off) ? s[tid - off] : 0;
        __syncthreads();
        s[tid] += t;
        __syncthreads();
    }
    if (i < N_NODES) g_row_start[i] = s[tid] - v;   // exclusive within block
    if (tid == SCAN_BS - 1) g_bsum[blockIdx.x] = s[tid];
}

// warp-scan of the 98 block sums
__global__ void scan2_k() {
    int lane = threadIdx.x;
    int carry = 0;
    for (int base = 0; base < SCAN_NB; base += 32) {
        int idx = base + lane;
        int v = (idx < SCAN_NB) ? g_bsum[idx] : 0;
        int incl = v;
        #pragma unroll
        for (int off = 1; off < 32; off <<= 1) {
            int t = __shfl_up_sync(0xffffffffu, incl, off);
            if (lane >= off) incl += t;
        }
        if (idx < SCAN_NB) g_boff[idx] = carry + incl - v;
        carry += __shfl_sync(0xffffffffu, incl, 31);
    }
}

__global__ void scan3_k() {
    int i = blockIdx.x * blockDim.x + threadIdx.x;
    if (i < N_NODES) {
        int rs = g_row_start[i] + g_boff[i / SCAN_BS];
        g_row_start[i] = rs;
        g_cursor[i]    = rs;
        g_dinv[i]      = rsqrtf((float)g_cnt[i] + 1.0f);
    }
    if (i == 0) g_row_start[N_NODES] = E_EDGES;
}

__global__ void place_k() {
    int e = blockIdx.x * blockDim.x + threadIdx.x;
    if (e >= E_EDGES) return;
    int pos = atomicAdd(&g_cursor[g_dstv[e]], 1);
    g_edge_src[pos] = g_srcv[e];
}

// ---------------- fused GEMM: hs = (in @ W) * dinv[row] ---------------------
#define WPAD 68
__global__ void __launch_bounds__(256)
gemm_scale_k(const float* __restrict__ xg, const float* __restrict__ W) {
    __shared__ float Ws[64 * WPAD];
    __shared__ float xT[64 * WPAD];

    const float* in = xg ? xg : g_h;
    const int tid  = threadIdx.x;
    const int row0 = blockIdx.x * 64;

    for (int i4 = tid; i4 < 1024; i4 += 256) {
        float4 v = ((const float4*)W)[i4];
        int lin = i4 * 4;
        int k = lin >> 6, c = lin & 63;
        *(float4*)&Ws[k * WPAD + c] = v;
    }
    {
        int r  = tid >> 2;
        int kq = (tid & 3) * 16;
        int rg = row0 + r;
        const float4* xrow = (const float4*)(in + (size_t)rg * D);
        #pragma unroll
        for (int kk = 0; kk < 16; kk += 4) {
            float4 v = (rg < N_NODES) ? xrow[(kq + kk) >> 2]
                                      : make_float4(0.f, 0.f, 0.f, 0.f);
            int k = kq + kk;
            xT[(k + 0) * WPAD + r] = v.x;
            xT[(k + 1) * WPAD + r] = v.y;
            xT[(k + 2) * WPAD + r] = v.z;
            xT[(k + 3) * WPAD + r] = v.w;
        }
    }
    __syncthreads();

    const int c0 = (tid & 15) * 4;
    const int r0 = (tid >> 4) * 4;

    float acc[4][4];
    #pragma unroll
    for (int i = 0; i < 4; i++)
        #pragma unroll
        for (int j = 0; j < 4; j++) acc[i][j] = 0.0f;

    #pragma unroll 16
    for (int k = 0; k < 64; k++) {
        float4 wv = *(float4*)&Ws[k * WPAD + c0];
        float4 xv = *(float4*)&xT[k * WPAD + r0];
        acc[0][0] += xv.x * wv.x; acc[0][1] += xv.x * wv.y;
        acc[0][2] += xv.x * wv.z; acc[0][3] += xv.x * wv.w;
        acc[1][0] += xv.y * wv.x; acc[1][1] += xv.y * wv.y;
        acc[1][2] += xv.y * wv.z; acc[1][3] += xv.y * wv.w;
        acc[2][0] += xv.z * wv.x; acc[2][1] += xv.z * wv.y;
        acc[2][2] += xv.z * wv.z; acc[2][3] += xv.z * wv.w;
        acc[3][0] += xv.w * wv.x; acc[3][1] += xv.w * wv.y;
        acc[3][2] += xv.w * wv.z; acc[3][3] += xv.w * wv.w;
    }

    #pragma unroll
    for (int i = 0; i < 4; i++) {
        int row = row0 + r0 + i;
        if (row < N_NODES) {
            float dv = g_dinv[row];
            *(float4*)&g_hs[(size_t)row * D + c0] =
                make_float4(acc[i][0] * dv, acc[i][1] * dv,
                            acc[i][2] * dv, acc[i][3] * dv);
        }
    }
}

// ---------------- CSR gather + epilogue -------------------------------------
// Half-warp per node: 16 lanes x float4 = 256B row. 2 nodes per warp.
// out[i] = dinv[i] * (sum_{e in CSR[i]} hs[src_e] + hs[i]) + b   (+relu)
__global__ void __launch_bounds__(256)
agg_k(const float* __restrict__ b, float* __restrict__ outp, int relu) {
    int warp  = (blockIdx.x * blockDim.x + threadIdx.x) >> 5;
    int lane  = threadIdx.x & 31;
    int half  = lane >> 4;            // 0 or 1
    int l     = lane & 15;            // lane within half-warp
    int node  = warp * 2 + half;
    if (node >= N_NODES) return;

    float* out = outp ? outp : g_h;
    const float4* hs4 = (const float4*)g_hs;

    int beg = g_row_start[node];
    int end = g_row_start[node + 1];

    float4 acc = __ldg(&hs4[(size_t)node * 16 + l]);   // self-loop term
    int e = beg;
    for (; e + 3 < end; e += 4) {
        int s0 = __ldg(&g_edge_src[e + 0]);
        int s1 = __ldg(&g_edge_src[e + 1]);
        int s2 = __ldg(&g_edge_src[e + 2]);
        int s3 = __ldg(&g_edge_src[e + 3]);
        float4 a0 = __ldg(&hs4[(size_t)s0 * 16 + l]);
        float4 a1 = __ldg(&hs4[(size_t)s1 * 16 + l]);
        float4 a2 = __ldg(&hs4[(size_t)s2 * 16 + l]);
        float4 a3 = __ldg(&hs4[(size_t)s3 * 16 + l]);
        acc.x += (a0.x + a1.x) + (a2.x + a3.x);
        acc.y += (a0.y + a1.y) + (a2.y + a3.y);
        acc.z += (a0.z + a1.z) + (a2.z + a3.z);
        acc.w += (a0.w + a1.w) + (a2.w + a3.w);
    }
    for (; e < end; e++) {
        int s0 = __ldg(&g_edge_src[e]);
        float4 a = __ldg(&hs4[(size_t)s0 * 16 + l]);
        acc.x += a.x; acc.y += a.y; acc.z += a.z; acc.w += a.w;
    }

    float dv = g_dinv[node];
    float4 bv = __ldg(&((const float4*)b)[l]);
    float4 o;
    o.x = acc.x * dv + bv.x;
    o.y = acc.y * dv + bv.y;
    o.z = acc.z * dv + bv.z;
    o.w = acc.w * dv + bv.w;
    if (relu) {
        o.x = fmaxf(o.x, 0.f); o.y = fmaxf(o.y, 0.f);
        o.z = fmaxf(o.z, 0.f); o.w = fmaxf(o.w, 0.f);
    }
    ((float4*)out)[(size_t)node * 16 + l] = o;
}

// ---------------- launch ----------------------------------------------------
extern "C" void kernel_launch(void* const* d_in, const int* in_sizes, int n_in,
                              void* d_out, int out_size) {
    const float* x  = (const float*)d_in[0];
    const void*  ei = d_in[1];                 // int32 (or int64), detected on device
    const float* W0 = (const float*)d_in[2];
    const float* b0 = (const float*)d_in[3];
    const float* W1 = (const float*)d_in[4];
    const float* b1 = (const float*)d_in[5];
    const float* W2 = (const float*)d_in[6];
    const float* b2 = (const float*)d_in[7];
    float* out = (float*)d_out;

    const int TB = 256;
    const int ngrid = (N_NODES + TB - 1) / TB;
    const int egrid = (E_EDGES + TB - 1) / TB;

    detect_k   <<<1, 32>>>((const int*)ei);
    zero_cnt_k <<<ngrid, TB>>>();
    conv_hist_k<<<egrid, TB>>>(ei);
    scan1_k    <<<SCAN_NB, SCAN_BS>>>();
    scan2_k    <<<1, 32>>>();
    scan3_k    <<<ngrid, TB>>>();
    place_k    <<<egrid, TB>>>();

    const int gemm_grid = (N_NODES + 63) / 64;
    const int agg_grid  = ((N_NODES + 1) / 2 * 32 + TB - 1) / TB;  // 2 nodes/warp

    // layer 0
    gemm_scale_k<<<gemm_grid, TB>>>(x, W0);
    agg_k       <<<agg_grid, TB>>>(b0, nullptr, 1);
    // layer 1
    gemm_scale_k<<<gemm_grid, TB>>>(nullptr, W1);
    agg_k       <<<agg_grid, TB>>>(b1, nullptr, 1);
    // layer 2 -> d_out, no relu
    gemm_scale_k<<<gemm_grid, TB>>>(nullptr, W2);
    agg_k       <<<agg_grid, TB>>>(b2, out, 0);
}

// round 8
// speedup vs baseline: 1.1025x; 1.0436x over previous
#include <cuda_runtime.h>
#include <cuda_fp16.h>

#define N_NODES 100000
#define E_EDGES 1600000
#define D 64
#define SCAN_BS 1024
#define SCAN_NB ((N_NODES + SCAN_BS - 1) / SCAN_BS)   // 98

// ---------------- scratch (static device globals; no allocation) ------------
__device__ uint2 g_hsh[N_NODES * 16];    // (h @ W) * dinv[row], fp16 (4 halves/uint2)
__device__ float g_h  [N_NODES * D];     // layer output ping buffer (fp32)
__device__ float g_dinv[N_NODES];
__device__ int   g_cnt[N_NODES];         // in-degree counts
__device__ int   g_row_start[N_NODES + 1];
__device__ int   g_cursor[N_NODES];
__device__ int   g_edge_src[E_EDGES];    // src ids grouped by dst (CSR)
__device__ int   g_bsum[SCAN_NB];
__device__ int   g_boff[SCAN_NB];
__device__ int   g_is64;                 // 1 if edge_index buffer is int64

// ---------------- dtype detection -------------------------------------------
// int64 little-endian nonneg ids => every odd int32 word is a zero high word.
__global__ void detect_k(const int* __restrict__ ei32) {
    if (threadIdx.x == 0 && blockIdx.x == 0) {
        int nz = 0;
        #pragma unroll
        for (int k = 0; k < 8; k++) nz |= ei32[2 * k + 1];
        g_is64 = (nz == 0) ? 1 : 0;
    }
}

__global__ void zero_cnt_k() {
    int i = blockIdx.x * blockDim.x + threadIdx.x;
    if (i < N_NODES) g_cnt[i] = 0;
}

// decode dst + degree histogram (no staging stores)
__global__ void hist_k(const void* __restrict__ eiv) {
    int e = blockIdx.x * blockDim.x + threadIdx.x;
    if (e >= E_EDGES) return;
    int d;
    if (g_is64) d = (int)((const long long*)eiv)[E_EDGES + e];
    else        d = ((const int*)eiv)[E_EDGES + e];
    d = min(max(d, 0), N_NODES - 1);
    atomicAdd(&g_cnt[d], 1);
}

// shuffle-based block scan (2 barriers)
__global__ void scan1_k() {
    __shared__ int warp_sums[32];
    int tid  = threadIdx.x;
    int wid  = tid >> 5;
    int lane = tid & 31;
    int i = blockIdx.x * SCAN_BS + tid;
    int v = (i < N_NODES) ? g_cnt[i] : 0;

    int incl = v;
    #pragma unroll
    for (int off = 1; off < 32; off <<= 1) {
        int t = __shfl_up_sync(0xffffffffu, incl, off);
        if (lane >= off) incl += t;
    }
    if (lane == 31) warp_sums[wid] = incl;
    __syncthreads();
    if (wid == 0) {
        int ws = warp_sums[lane];
        int wincl = ws;
        #pragma unroll
        for (int off = 1; off < 32; off <<= 1) {
            int t = __shfl_up_sync(0xffffffffu, wincl, off);
            if (lane >= off) wincl += t;
        }
        warp_sums[lane] = wincl - ws;   // exclusive warp offsets
        if (lane == 31) g_bsum[blockIdx.x] = wincl;
    }
    __syncthreads();
    if (i < N_NODES) g_row_start[i] = warp_sums[wid] + incl - v;  // exclusive
}

// warp-scan of the 98 block sums
__global__ void scan2_k() {
    int lane = threadIdx.x;
    int carry = 0;
    for (int base = 0; base < SCAN_NB; base += 32) {
        int idx = base + lane;
        int v = (idx < SCAN_NB) ? g_bsum[idx] : 0;
        int incl = v;
        #pragma unroll
        for (int off = 1; off < 32; off <<= 1) {
            int t = __shfl_up_sync(0xffffffffu, incl, off);
            if (lane >= off) incl += t;
        }
        if (idx < SCAN_NB) g_boff[idx] = carry + incl - v;
        carry += __shfl_sync(0xffffffffu, incl, 31);
    }
}

__global__ void scan3_k() {
    int i = blockIdx.x * blockDim.x + threadIdx.x;
    if (i < N_NODES) {
        int rs = g_row_start[i] + g_boff[i / SCAN_BS];
        g_row_start[i] = rs;
        g_cursor[i]    = rs;
        g_dinv[i]      = rsqrtf((float)g_cnt[i] + 1.0f);
    }
    if (i == 0) g_row_start[N_NODES] = E_EDGES;
}

// re-decode src+dst from original buffer; scatter src into CSR slots
__global__ void place_k(const void* __restrict__ eiv) {
    int e = blockIdx.x * blockDim.x + threadIdx.x;
    if (e >= E_EDGES) return;
    int s, d;
    if (g_is64) {
        const long long* ei = (const long long*)eiv;
        s = (int)ei[e];
        d = (int)ei[E_EDGES + e];
    } else {
        const int* ei = (const int*)eiv;
        s = ei[e];
        d = ei[E_EDGES + e];
    }
    s = min(max(s, 0), N_NODES - 1);
    d = min(max(d, 0), N_NODES - 1);
    int pos = atomicAdd(&g_cursor[d], 1);
    g_edge_src[pos] = s;
}

// ---------------- fused GEMM: hsh = fp16((in @ W) * dinv[row]) --------------
#define WPAD 68
__global__ void __launch_bounds__(256)
gemm_scale_k(const float* __restrict__ xg, const float* __restrict__ W) {
    __shared__ float Ws[64 * WPAD];
    __shared__ float xT[64 * WPAD];

    const float* in = xg ? xg : g_h;
    const int tid  = threadIdx.x;
    const int row0 = blockIdx.x * 64;

    for (int i4 = tid; i4 < 1024; i4 += 256) {
        float4 v = ((const float4*)W)[i4];
        int lin = i4 * 4;
        int k = lin >> 6, c = lin & 63;
        *(float4*)&Ws[k * WPAD + c] = v;
    }
    {
        int r  = tid >> 2;
        int kq = (tid & 3) * 16;
        int rg = row0 + r;
        const float4* xrow = (const float4*)(in + (size_t)rg * D);
        #pragma unroll
        for (int kk = 0; kk < 16; kk += 4) {
            float4 v = (rg < N_NODES) ? xrow[(kq + kk) >> 2]
                                      : make_float4(0.f, 0.f, 0.f, 0.f);
            int k = kq + kk;
            xT[(k + 0) * WPAD + r] = v.x;
            xT[(k + 1) * WPAD + r] = v.y;
            xT[(k + 2) * WPAD + r] = v.z;
            xT[(k + 3) * WPAD + r] = v.w;
        }
    }
    __syncthreads();

    const int c0 = (tid & 15) * 4;
    const int r0 = (tid >> 4) * 4;

    float acc[4][4];
    #pragma unroll
    for (int i = 0; i < 4; i++)
        #pragma unroll
        for (int j = 0; j < 4; j++) acc[i][j] = 0.0f;

    #pragma unroll 16
    for (int k = 0; k < 64; k++) {
        float4 wv = *(float4*)&Ws[k * WPAD + c0];
        float4 xv = *(float4*)&xT[k * WPAD + r0];
        acc[0][0] += xv.x * wv.x; acc[0][1] += xv.x * wv.y;
        acc[0][2] += xv.x * wv.z; acc[0][3] += xv.x * wv.w;
        acc[1][0] += xv.y * wv.x; acc[1][1] += xv.y * wv.y;
        acc[1][2] += xv.y * wv.z; acc[1][3] += xv.y * wv.w;
        acc[2][0] += xv.z * wv.x; acc[2][1] += xv.z * wv.y;
        acc[2][2] += xv.z * wv.z; acc[2][3] += xv.z * wv.w;
        acc[3][0] += xv.w * wv.x; acc[3][1] += xv.w * wv.y;
        acc[3][2] += xv.w * wv.z; acc[3][3] += xv.w * wv.w;
    }

    #pragma unroll
    for (int i = 0; i < 4; i++) {
        int row = row0 + r0 + i;
        if (row < N_NODES) {
            float dv = g_dinv[row];
            __half2 h0 = __floats2half2_rn(acc[i][0] * dv, acc[i][1] * dv);
            __half2 h1 = __floats2half2_rn(acc[i][2] * dv, acc[i][3] * dv);
            uint2 u;
            u.x = *(unsigned*)&h0;
            u.y = *(unsigned*)&h1;
            g_hsh[(size_t)row * 16 + (c0 >> 2)] = u;
        }
    }
}

// ---------------- CSR gather + epilogue -------------------------------------
// Half-warp per node: 16 lanes x 4 halves (8B) = 128B row. 2 nodes per warp.
// out[i] = dinv[i] * (sum_{e in CSR[i]} hs[src_e] + hs[i]) + b   (+relu)
__global__ void __launch_bounds__(256)
agg_k(const float* __restrict__ b, float* __restrict__ outp, int relu) {
    int warp  = (blockIdx.x * blockDim.x + threadIdx.x) >> 5;
    int lane  = threadIdx.x & 31;
    int half  = lane >> 4;
    int l     = lane & 15;
    int node  = warp * 2 + half;
    if (node >= N_NODES) return;

    float* out = outp ? outp : g_h;

    int beg = g_row_start[node];
    int end = g_row_start[node + 1];

    float4 acc;
    {   // self-loop term
        uint2 u = __ldg(&g_hsh[(size_t)node * 16 + l]);
        float2 f0 = __half22float2(*(__half2*)&u.x);
        float2 f1 = __half22float2(*(__half2*)&u.y);
        acc = make_float4(f0.x, f0.y, f1.x, f1.y);
    }
    int e = beg;
    for (; e + 3 < end; e += 4) {
        int s0 = __ldg(&g_edge_src[e + 0]);
        int s1 = __ldg(&g_edge_src[e + 1]);
        int s2 = __ldg(&g_edge_src[e + 2]);
        int s3 = __ldg(&g_edge_src[e + 3]);
        uint2 u0 = __ldg(&g_hsh[(size_t)s0 * 16 + l]);
        uint2 u1 = __ldg(&g_hsh[(size_t)s1 * 16 + l]);
        uint2 u2 = __ldg(&g_hsh[(size_t)s2 * 16 + l]);
        uint2 u3 = __ldg(&g_hsh[(size_t)s3 * 16 + l]);
        float2 a0 = __half22float2(*(__half2*)&u0.x), b0_ = __half22float2(*(__half2*)&u0.y);
        float2 a1 = __half22float2(*(__half2*)&u1.x), b1_ = __half22float2(*(__half2*)&u1.y);
        float2 a2 = __half22float2(*(__half2*)&u2.x), b2_ = __half22float2(*(__half2*)&u2.y);
        float2 a3 = __half22float2(*(__half2*)&u3.x), b3_ = __half22float2(*(__half2*)&u3.y);
        acc.x += (a0.x + a1.x) + (a2.x + a3.x);
        acc.y += (a0.y + a1.y) + (a2.y + a3.y);
        acc.z += (b0_.x + b1_.x) + (b2_.x + b3_.x);
        acc.w += (b0_.y + b1_.y) + (b2_.y + b3_.y);
    }
    for (; e < end; e++) {
        int s0 = __ldg(&g_edge_src[e]);
        uint2 u = __ldg(&g_hsh[(size_t)s0 * 16 + l]);
        float2 f0 = __half22float2(*(__half2*)&u.x);
        float2 f1 = __half22float2(*(__half2*)&u.y);
        acc.x += f0.x; acc.y += f0.y; acc.z += f1.x; acc.w += f1.y;
    }

    float dv = g_dinv[node];
    float4 bv = __ldg(&((const float4*)b)[l]);
    float4 o;
    o.x = acc.x * dv + bv.x;
    o.y = acc.y * dv + bv.y;
    o.z = acc.z * dv + bv.z;
    o.w = acc.w * dv + bv.w;
    if (relu) {
        o.x = fmaxf(o.x, 0.f); o.y = fmaxf(o.y, 0.f);
        o.z = fmaxf(o.z, 0.f); o.w = fmaxf(o.w, 0.f);
    }
    ((float4*)out)[(size_t)node * 16 + l] = o;
}

// ---------------- launch ----------------------------------------------------
extern "C" void kernel_launch(void* const* d_in, const int* in_sizes, int n_in,
                              void* d_out, int out_size) {
    const float* x  = (const float*)d_in[0];
    const void*  ei = d_in[1];                 // int32 (or int64), detected on device
    const float* W0 = (const float*)d_in[2];
    const float* b0 = (const float*)d_in[3];
    const float* W1 = (const float*)d_in[4];
    const float* b1 = (const float*)d_in[5];
    const float* W2 = (const float*)d_in[6];
    const float* b2 = (const float*)d_in[7];
    float* out = (float*)d_out;

    const int TB = 256;
    const int ngrid = (N_NODES + TB - 1) / TB;
    const int egrid = (E_EDGES + TB - 1) / TB;

    detect_k  <<<1, 32>>>((const int*)ei);
    zero_cnt_k<<<ngrid, TB>>>();
    hist_k    <<<egrid, TB>>>(ei);
    scan1_k   <<<SCAN_NB, SCAN_BS>>>();
    scan2_k   <<<1, 32>>>();
    scan3_k   <<<ngrid, TB>>>();
    place_k   <<<egrid, TB>>>(ei);

    const int gemm_grid = (N_NODES + 63) / 64;
    const int agg_grid  = ((N_NODES + 1) / 2 * 32 + TB - 1) / TB;  // 2 nodes/warp

    // layer 0
    gemm_scale_k<<<gemm_grid, TB>>>(x, W0);
    agg_k       <<<agg_grid, TB>>>(b0, nullptr, 1);
    // layer 1
    gemm_scale_k<<<gemm_grid, TB>>>(nullptr, W1);
    agg_k       <<<agg_grid, TB>>>(b1, nullptr, 1);
    // layer 2 -> d_out, no relu
    gemm_scale_k<<<gemm_grid, TB>>>(nullptr, W2);
    agg_k       <<<agg_grid, TB>>>(b2, out, 0);
}

// round 9
// speedup vs baseline: 1.1256x; 1.0209x over previous
#include <cuda_runtime.h>
#include <cuda_fp16.h>

#define N_NODES 100000
#define E_EDGES 1600000
#define D 64
#define SCAN_BS 1024
#define SCAN_NB ((N_NODES + SCAN_BS - 1) / SCAN_BS)   // 98

// ---------------- scratch (static device globals; no allocation) ------------
__device__ uint2 g_hsh[N_NODES * 16];    // (h @ W) * dinv[row], fp16 (4 halves/uint2)
__device__ float g_h  [N_NODES * D];     // layer output ping buffer (fp32)
__device__ float g_dinv[N_NODES];
__device__ int   g_cnt[N_NODES];         // in-degree counts
__device__ int   g_row_start[N_NODES + 1];
__device__ int   g_cursor[N_NODES];
__device__ int   g_edge_src[E_EDGES];    // src ids grouped by dst (CSR)
__device__ int   g_bsum[SCAN_NB];
__device__ int   g_is64;                 // 1 if edge_index buffer is int64

// ---------------- zero counts + dtype detection (merged) --------------------
// int64 little-endian nonneg ids => every odd int32 word is a zero high word.
__global__ void zero_detect_k(const int* __restrict__ ei32) {
    int i = blockIdx.x * blockDim.x + threadIdx.x;
    if (i < N_NODES) g_cnt[i] = 0;
    if (i == 0) {
        int nz = 0;
        #pragma unroll
        for (int k = 0; k < 8; k++) nz |= ei32[2 * k + 1];
        g_is64 = (nz == 0) ? 1 : 0;
    }
}

// decode dst + degree histogram (no staging stores)
__global__ void hist_k(const void* __restrict__ eiv) {
    int e = blockIdx.x * blockDim.x + threadIdx.x;
    if (e >= E_EDGES) return;
    int d;
    if (g_is64) d = (int)((const long long*)eiv)[E_EDGES + e];
    else        d = ((const int*)eiv)[E_EDGES + e];
    d = min(max(d, 0), N_NODES - 1);
    atomicAdd(&g_cnt[d], 1);
}

// shuffle-based block scan (2 barriers)
__global__ void scan1_k() {
    __shared__ int warp_sums[32];
    int tid  = threadIdx.x;
    int wid  = tid >> 5;
    int lane = tid & 31;
    int i = blockIdx.x * SCAN_BS + tid;
    int v = (i < N_NODES) ? g_cnt[i] : 0;

    int incl = v;
    #pragma unroll
    for (int off = 1; off < 32; off <<= 1) {
        int t = __shfl_up_sync(0xffffffffu, incl, off);
        if (lane >= off) incl += t;
    }
    if (lane == 31) warp_sums[wid] = incl;
    __syncthreads();
    if (wid == 0) {
        int ws = warp_sums[lane];
        int wincl = ws;
        #pragma unroll
        for (int off = 1; off < 32; off <<= 1) {
            int t = __shfl_up_sync(0xffffffffu, wincl, off);
            if (lane >= off) wincl += t;
        }
        warp_sums[lane] = wincl - ws;   // exclusive warp offsets
        if (lane == 31) g_bsum[blockIdx.x] = wincl;
    }
    __syncthreads();
    if (i < N_NODES) g_row_start[i] = warp_sums[wid] + incl - v;  // exclusive
}

// scan3 with scan2 folded in: each block computes its 1-2 needed block-prefix
// sums over the 98 g_bsum entries (warp reduction, redundant but tiny).
__global__ void scan3_k() {
    __shared__ int sboff[2];
    int i0  = blockIdx.x * 256;
    int sb0 = i0 >> 10;                       // scan1 block of first element
    int sb1 = (i0 + 255) >> 10;               // scan1 block of last element
    int wid = threadIdx.x >> 5, lane = threadIdx.x & 31;
    if (wid < 2) {
        int target = (wid == 0) ? sb0 : sb1;  // sum g_bsum[0..target-1]
        int s = 0;
        for (int b = lane; b < target; b += 32) s += g_bsum[b];
        #pragma unroll
        for (int off = 16; off; off >>= 1) s += __shfl_down_sync(0xffffffffu, s, off);
        if (lane == 0) sboff[wid] = s;
    }
    __syncthreads();
    int i = i0 + threadIdx.x;
    if (i < N_NODES) {
        int off = sboff[((i >> 10) == sb0) ? 0 : 1];
        int rs = g_row_start[i] + off;
        g_row_start[i] = rs;
        g_cursor[i]    = rs;
        g_dinv[i]      = rsqrtf((float)g_cnt[i] + 1.0f);
    }
    if (i == 0) g_row_start[N_NODES] = E_EDGES;
}

// re-decode src+dst from original buffer; scatter src into CSR slots
__global__ void place_k(const void* __restrict__ eiv) {
    int e = blockIdx.x * blockDim.x + threadIdx.x;
    if (e >= E_EDGES) return;
    int s, d;
    if (g_is64) {
        const long long* ei = (const long long*)eiv;
        s = (int)ei[e];
        d = (int)ei[E_EDGES + e];
    } else {
        const int* ei = (const int*)eiv;
        s = ei[e];
        d = ei[E_EDGES + e];
    }
    s = min(max(s, 0), N_NODES - 1);
    d = min(max(d, 0), N_NODES - 1);
    int pos = atomicAdd(&g_cursor[d], 1);
    g_edge_src[pos] = s;
}

// ---------------- fused GEMM: hsh = fp16((in @ W) * dinv[row]) --------------
#define WPAD 68
__global__ void __launch_bounds__(256)
gemm_scale_k(const float* __restrict__ xg, const float* __restrict__ W) {
    __shared__ float Ws[64 * WPAD];
    __shared__ float xT[64 * WPAD];

    const float* in = xg ? xg : g_h;
    const int tid  = threadIdx.x;
    const int row0 = blockIdx.x * 64;

    for (int i4 = tid; i4 < 1024; i4 += 256) {
        float4 v = ((const float4*)W)[i4];
        int lin = i4 * 4;
        int k = lin >> 6, c = lin & 63;
        *(float4*)&Ws[k * WPAD + c] = v;
    }
    {
        int r  = tid >> 2;
        int kq = (tid & 3) * 16;
        int rg = row0 + r;
        const float4* xrow = (const float4*)(in + (size_t)rg * D);
        #pragma unroll
        for (int kk = 0; kk < 16; kk += 4) {
            float4 v = (rg < N_NODES) ? xrow[(kq + kk) >> 2]
                                      : make_float4(0.f, 0.f, 0.f, 0.f);
            int k = kq + kk;
            xT[(k + 0) * WPAD + r] = v.x;
            xT[(k + 1) * WPAD + r] = v.y;
            xT[(k + 2) * WPAD + r] = v.z;
            xT[(k + 3) * WPAD + r] = v.w;
        }
    }
    __syncthreads();

    const int c0 = (tid & 15) * 4;
    const int r0 = (tid >> 4) * 4;

    float acc[4][4];
    #pragma unroll
    for (int i = 0; i < 4; i++)
        #pragma unroll
        for (int j = 0; j < 4; j++) acc[i][j] = 0.0f;

    #pragma unroll 16
    for (int k = 0; k < 64; k++) {
        float4 wv = *(float4*)&Ws[k * WPAD + c0];
        float4 xv = *(float4*)&xT[k * WPAD + r0];
        acc[0][0] += xv.x * wv.x; acc[0][1] += xv.x * wv.y;
        acc[0][2] += xv.x * wv.z; acc[0][3] += xv.x * wv.w;
        acc[1][0] += xv.y * wv.x; acc[1][1] += xv.y * wv.y;
        acc[1][2] += xv.y * wv.z; acc[1][3] += xv.y * wv.w;
        acc[2][0] += xv.z * wv.x; acc[2][1] += xv.z * wv.y;
        acc[2][2] += xv.z * wv.z; acc[2][3] += xv.z * wv.w;
        acc[3][0] += xv.w * wv.x; acc[3][1] += xv.w * wv.y;
        acc[3][2] += xv.w * wv.z; acc[3][3] += xv.w * wv.w;
    }

    #pragma unroll
    for (int i = 0; i < 4; i++) {
        int row = row0 + r0 + i;
        if (row < N_NODES) {
            float dv = g_dinv[row];
            __half2 h0 = __floats2half2_rn(acc[i][0] * dv, acc[i][1] * dv);
            __half2 h1 = __floats2half2_rn(acc[i][2] * dv, acc[i][3] * dv);
            uint2 u;
            u.x = *(unsigned*)&h0;
            u.y = *(unsigned*)&h1;
            g_hsh[(size_t)row * 16 + (c0 >> 2)] = u;
        }
    }
}

// ---------------- CSR gather + epilogue -------------------------------------
// Half-warp per node, shuffle-batched: lanes cooperatively load up to 16 edge
// indices with ONE coalesced LDG, broadcast via shfl, then issue up to 16
// independent row gathers (max MLP).
__global__ void __launch_bounds__(256)
agg_k(const float* __restrict__ b, float* __restrict__ outp, int relu) {
    int warp  = (blockIdx.x * blockDim.x + threadIdx.x) >> 5;
    int lane  = threadIdx.x & 31;
    int half  = lane >> 4;
    int l     = lane & 15;
    int node  = warp * 2 + half;
    if (node >= N_NODES) return;

    unsigned hmask = half ? 0xffff0000u : 0x0000ffffu;
    float* out = outp ? outp : g_h;

    int beg = g_row_start[node];
    int end = g_row_start[node + 1];

    float4 acc;
    {   // self-loop term
        uint2 u = __ldg(&g_hsh[(size_t)node * 16 + l]);
        float2 f0 = __half22float2(*(__half2*)&u.x);
        float2 f1 = __half22float2(*(__half2*)&u.y);
        acc = make_float4(f0.x, f0.y, f1.x, f1.y);
    }

    for (int base = beg; base < end; base += 16) {
        int n = end - base; if (n > 16) n = 16;
        int myidx = (l < n) ? __ldg(&g_edge_src[base + l]) : 0;
        int j = 0;
        for (; j + 3 < n; j += 4) {
            int s0 = __shfl_sync(hmask, myidx, j + 0, 16);
            int s1 = __shfl_sync(hmask, myidx, j + 1, 16);
            int s2 = __shfl_sync(hmask, myidx, j + 2, 16);
            int s3 = __shfl_sync(hmask, myidx, j + 3, 16);
            uint2 u0 = __ldg(&g_hsh[(size_t)s0 * 16 + l]);
            uint2 u1 = __ldg(&g_hsh[(size_t)s1 * 16 + l]);
            uint2 u2 = __ldg(&g_hsh[(size_t)s2 * 16 + l]);
            uint2 u3 = __ldg(&g_hsh[(size_t)s3 * 16 + l]);
            float2 a0 = __half22float2(*(__half2*)&u0.x), c0 = __half22float2(*(__half2*)&u0.y);
            float2 a1 = __half22float2(*(__half2*)&u1.x), c1 = __half22float2(*(__half2*)&u1.y);
            float2 a2 = __half22float2(*(__half2*)&u2.x), c2 = __half22float2(*(__half2*)&u2.y);
            float2 a3 = __half22float2(*(__half2*)&u3.x), c3 = __half22float2(*(__half2*)&u3.y);
            acc.x += (a0.x + a1.x) + (a2.x + a3.x);
            acc.y += (a0.y + a1.y) + (a2.y + a3.y);
            acc.z += (c0.x + c1.x) + (c2.x + c3.x);
            acc.w += (c0.y + c1.y) + (c2.y + c3.y);
        }
        for (; j < n; j++) {
            int s0 = __shfl_sync(hmask, myidx, j, 16);
            uint2 u = __ldg(&g_hsh[(size_t)s0 * 16 + l]);
            float2 f0 = __half22float2(*(__half2*)&u.x);
            float2 f1 = __half22float2(*(__half2*)&u.y);
            acc.x += f0.x; acc.y += f0.y; acc.z += f1.x; acc.w += f1.y;
        }
    }

    float dv = g_dinv[node];
    float4 bv = __ldg(&((const float4*)b)[l]);
    float4 o;
    o.x = acc.x * dv + bv.x;
    o.y = acc.y * dv + bv.y;
    o.z = acc.z * dv + bv.z;
    o.w = acc.w * dv + bv.w;
    if (relu) {
        o.x = fmaxf(o.x, 0.f); o.y = fmaxf(o.y, 0.f);
        o.z = fmaxf(o.z, 0.f); o.w = fmaxf(o.w, 0.f);
    }
    ((float4*)out)[(size_t)node * 16 + l] = o;
}

// ---------------- launch ----------------------------------------------------
extern "C" void kernel_launch(void* const* d_in, const int* in_sizes, int n_in,
                              void* d_out, int out_size) {
    const float* x  = (const float*)d_in[0];
    const void*  ei = d_in[1];                 // int32 (or int64), detected on device
    const float* W0 = (const float*)d_in[2];
    const float* b0 = (const float*)d_in[3];
    const float* W1 = (const float*)d_in[4];
    const float* b1 = (const float*)d_in[5];
    const float* W2 = (const float*)d_in[6];
    const float* b2 = (const float*)d_in[7];
    float* out = (float*)d_out;

    const int TB = 256;
    const int ngrid = (N_NODES + TB - 1) / TB;
    const int egrid = (E_EDGES + TB - 1) / TB;

    zero_detect_k<<<ngrid, TB>>>((const int*)ei);
    hist_k       <<<egrid, TB>>>(ei);
    scan1_k      <<<SCAN_NB, SCAN_BS>>>();
    scan3_k      <<<ngrid, TB>>>();
    place_k      <<<egrid, TB>>>(ei);

    const int gemm_grid = (N_NODES + 63) / 64;
    const int agg_grid  = ((N_NODES + 1) / 2 * 32 + TB - 1) / TB;  // 2 nodes/warp

    // layer 0
    gemm_scale_k<<<gemm_grid, TB>>>(x, W0);
    agg_k       <<<agg_grid, TB>>>(b0, nullptr, 1);
    // layer 1
    gemm_scale_k<<<gemm_grid, TB>>>(nullptr, W1);
    agg_k       <<<agg_grid, TB>>>(b1, nullptr, 1);
    // layer 2 -> d_out, no relu
    gemm_scale_k<<<gemm_grid, TB>>>(nullptr, W2);
    agg_k       <<<agg_grid, TB>>>(b2, out, 0);
}